// round 10
// baseline (speedup 1.0000x reference)
#include <cuda_runtime.h>

#define T_LEN 1024

struct Pr {
    float INSC, COEFF, SMSC, SUB10, CRAK10, RecK, kGW, inv10, cexp2;
};

__device__ __forceinline__ float ex2f(float x) {
    float r; asm("ex2.approx.ftz.f32 %0, %1;" : "=f"(r) : "f"(x)); return r;
}

// One scan step on pre-clipped state SMSc in [0, SMSC], GW >= 0.
// Returns Q[t] for the state ENTERING the step (matches reference's roll(1)).
__device__ __forceinline__ float stepQ(float Prec, float PET,
                                       float& SMSc, float& GW, const Pr& p)
{
    float arg  = SMSc * p.cexp2;                 // exp2 argument (log2e folded)
    float tf   = SMSc * p.inv10;                 // 10 * SMSc / SMSC
    float INT  = fminf(fminf(p.INSC, PET), Prec);
    float INR  = Prec - INT;
    float POT  = PET - INT;
    float ETS  = fminf(POT, tf);
    float a1   = fmaf(-p.SUB10,  tf, 1.0f);      // 1 - SUB*frac
    float a2   = fmaf(-p.CRAK10, tf, 1.0f);      // 1 - CRAK*frac
    float g    = a1 * a2;
    float base = SMSc - ETS;
    float cap  = p.COEFF * ex2f(arg);            // COEFF * exp(-SQ*frac)
    float RMO  = fminf(INR, cap);                // heaviside blend == min
    float s    = fmaf(RMO, g, base);             // next SMS (pre-clip)
    float h    = RMO * a1;                       // RMO - SRUN
    float ns   = fminf(s, p.SMSC);               // clipped next store
    float RECn = h + (base - ns);                // REC + overflow (s cancels)
    float Q    = fmaf(p.RecK, GW, INR - h);      // (IRUN+SRUN) + BAS
    GW   = fmaf(GW, p.kGW, RECn);                // GW*(1-RecK) + RECn
    SMSc = ns;
    return Q;
}

#define STEP4(A, C, qi)                                   \
    do {                                                  \
        float4 q;                                         \
        q.x = stepQ(A.x, A.y, SMS, GW, p);                \
        q.y = stepQ(A.z, A.w, SMS, GW, p);                \
        q.z = stepQ(C.x, C.y, SMS, GW, p);                \
        q.w = stepQ(C.z, C.w, SMS, GW, p);                \
        qo[qi] = q;                                       \
    } while (0)

__global__ void __launch_bounds__(32)
hirnn_kernel(const float* __restrict__ in, float* __restrict__ out,
             const float* __restrict__ pINSC, const float* __restrict__ pCOEFF,
             const float* __restrict__ pSQ,   const float* __restrict__ pSMSC,
             const float* __restrict__ pSUB,  const float* __restrict__ pCRAK,
             const float* __restrict__ pRecK, int B)
{
    int b = blockIdx.x * 32 + threadIdx.x;
    if (b >= B) return;

    Pr p;
    p.INSC      = fminf(fmaxf(pINSC[0]  * 5.0f,   0.5f),   5.0f);
    p.COEFF     = fminf(fmaxf(pCOEFF[0] * 400.0f, 50.0f),  400.0f);
    float SQ    = fminf(fmaxf(pSQ[0]    * 6.0f,   0.0f),   6.0f);
    p.SMSC      = fminf(fmaxf(pSMSC[0]  * 500.0f, 50.0f),  500.0f);
    float SUB   = fminf(fmaxf(pSUB[0],            0.0f),   1.0f);
    float CRAK  = fminf(fmaxf(pCRAK[0],           0.0f),   1.0f);
    p.RecK      = fminf(fmaxf(pRecK[0]  * 0.3f,   0.003f), 0.3f);
    p.kGW       = 1.0f - p.RecK;
    float invS  = 1.0f / p.SMSC;
    p.inv10     = 10.0f * invS;
    p.SUB10     = SUB  * 0.1f;
    p.CRAK10    = CRAK * 0.1f;
    p.cexp2     = -SQ * invS * 1.44269504088896f;

    const float4* ip = reinterpret_cast<const float4*>(in + (size_t)b * (2 * T_LEN));
    float4*       qo = reinterpret_cast<float4*>(out + (size_t)b * T_LEN);

    float SMS = 0.0f, GW = 0.0f;

    // Software pipeline, distance = 2 groups (8 steps), scalar ping-pong
    // buffers (no register arrays -> no MOV shuffling). Group g's inputs are
    // ip[2g], ip[2g+1]. At iteration i we consume groups i, i+1 and refill
    // with groups i+2, i+3 (ld = 2i+4). L2 prefetch ~64 groups ahead turns
    // the refills into L2 hits, which the 8-step distance covers.
    float4 A0 = ip[0], C0 = ip[1];
    float4 A1 = ip[2], C1 = ip[3];

    #pragma unroll 1
    for (int i = 0; i < 256; i += 2) {       // i = group of 4 timesteps
        // prefetch this thread's input line 2KB ahead (clamped in-bounds)
        const float4* pf = ip + min(2 * i + 128, 508);
        asm volatile("prefetch.global.L2 [%0];" :: "l"(pf));

        STEP4(A0, C0, i);
        int ld = min(2 * i + 4, 508);        // groups i+2, i+3 (clamped tail)
        A0 = ip[ld];
        C0 = ip[ld + 1];

        STEP4(A1, C1, i + 1);
        A1 = ip[ld + 2];
        C1 = ip[ld + 3];
    }

    // Q[0]: roll wraps the FINAL state to t=0 — one extra step, t=0 inputs.
    float2 x0 = reinterpret_cast<const float2*>(in + (size_t)b * (2 * T_LEN))[0];
    out[(size_t)b * T_LEN] = stepQ(x0.x, x0.y, SMS, GW, p);
}

extern "C" void kernel_launch(void* const* d_in, const int* in_sizes, int n_in,
                              void* d_out, int out_size)
{
    const float* in = (const float*)d_in[0];
    int B = in_sizes[0] / (2 * T_LEN);
    int block = 32;                       // 1 warp/block -> spread over ~all SMs
    int grid  = (B + block - 1) / block;
    hirnn_kernel<<<grid, block>>>(in, (float*)d_out,
                                  (const float*)d_in[1], (const float*)d_in[2],
                                  (const float*)d_in[3], (const float*)d_in[4],
                                  (const float*)d_in[5], (const float*)d_in[6],
                                  (const float*)d_in[7], B);
}

// round 11
// speedup vs baseline: 1.9240x; 1.9240x over previous
#include <cuda_runtime.h>
#include <cstdint>

#define T_LEN 1024
#define NCH   64          // 64 chunks of 16 timesteps (8 float4 per thread)

struct Pr {
    float INSC, COEFF, SMSC, SUB10, CRAK10, RecK, kGW, inv10, cexp2;
};

__device__ __forceinline__ float ex2f(float x) {
    float r; asm("ex2.approx.ftz.f32 %0, %1;" : "=f"(r) : "f"(x)); return r;
}

__device__ __forceinline__ void cp16(uint32_t smem_dst, const void* gsrc) {
    asm volatile("cp.async.ca.shared.global [%0], [%1], 16;"
                 :: "r"(smem_dst), "l"(gsrc));
}

// One scan step on pre-clipped state SMSc in [0, SMSC], GW >= 0.
// Returns Q[t] for the state ENTERING the step (matches reference's roll(1)).
__device__ __forceinline__ float stepQ(float Prec, float PET,
                                       float& SMSc, float& GW, const Pr& p)
{
    float arg  = SMSc * p.cexp2;                 // exp2 argument (log2e folded)
    float tf   = SMSc * p.inv10;                 // 10 * SMSc / SMSC
    float INT  = fminf(fminf(p.INSC, PET), Prec);
    float INR  = Prec - INT;
    float POT  = PET - INT;
    float ETS  = fminf(POT, tf);
    float a1   = fmaf(-p.SUB10,  tf, 1.0f);      // 1 - SUB*frac
    float a2   = fmaf(-p.CRAK10, tf, 1.0f);      // 1 - CRAK*frac
    float g    = a1 * a2;
    float base = SMSc - ETS;
    float cap  = p.COEFF * ex2f(arg);            // COEFF * exp(-SQ*frac)
    float RMO  = fminf(INR, cap);                // heaviside blend == min
    float s    = fmaf(RMO, g, base);             // next SMS (pre-clip)
    float h    = RMO * a1;                       // RMO - SRUN
    float ns   = fminf(s, p.SMSC);               // clipped next store
    float RECn = h + (base - ns);                // REC + overflow (s cancels)
    float Q    = fmaf(p.RecK, GW, INR - h);      // (IRUN+SRUN) + BAS
    GW   = fmaf(GW, p.kGW, RECn);                // GW*(1-RecK) + RECn
    SMSc = ns;
    return Q;
}

__global__ void __launch_bounds__(32)
hirnn_kernel(const float* __restrict__ in, float* __restrict__ out,
             const float* __restrict__ pINSC, const float* __restrict__ pCOEFF,
             const float* __restrict__ pSQ,   const float* __restrict__ pSMSC,
             const float* __restrict__ pSUB,  const float* __restrict__ pCRAK,
             const float* __restrict__ pRecK, int B)
{
    // 4-slot ring of chunks: [slot][slice j][thread] — threads at contiguous
    // 16B stride per slice => conflict-free LDS.128 / cp.async stores.
    __shared__ float4 sb[4][8][32];

    int t = threadIdx.x;
    int b = blockIdx.x * 32 + t;
    if (b >= B) return;

    Pr p;
    p.INSC      = fminf(fmaxf(pINSC[0]  * 5.0f,   0.5f),   5.0f);
    p.COEFF     = fminf(fmaxf(pCOEFF[0] * 400.0f, 50.0f),  400.0f);
    float SQ    = fminf(fmaxf(pSQ[0]    * 6.0f,   0.0f),   6.0f);
    p.SMSC      = fminf(fmaxf(pSMSC[0]  * 500.0f, 50.0f),  500.0f);
    float SUB   = fminf(fmaxf(pSUB[0],            0.0f),   1.0f);
    float CRAK  = fminf(fmaxf(pCRAK[0],           0.0f),   1.0f);
    p.RecK      = fminf(fmaxf(pRecK[0]  * 0.3f,   0.003f), 0.3f);
    p.kGW       = 1.0f - p.RecK;
    float invS  = 1.0f / p.SMSC;
    p.inv10     = 10.0f * invS;
    p.SUB10     = SUB  * 0.1f;
    p.CRAK10    = CRAK * 0.1f;
    p.cexp2     = -SQ * invS * 1.44269504088896f;

    const float4* ip = reinterpret_cast<const float4*>(in + (size_t)b * (2 * T_LEN));
    float4*       qo = reinterpret_cast<float4*>(out + (size_t)b * T_LEN);

    float SMS = 0.0f, GW = 0.0f;

    // Prologue: prefetch chunks 0 and 1 (distance 2 => ~32 steps of cover).
    #pragma unroll
    for (int c0 = 0; c0 < 2; ++c0) {
        uint32_t dst = (uint32_t)__cvta_generic_to_shared(&sb[c0][0][t]);
        const float4* src = ip + c0 * 8;
        #pragma unroll
        for (int j = 0; j < 8; ++j)
            cp16(dst + j * (32 * 16), src + j);
        asm volatile("cp.async.commit_group;");
    }

    #pragma unroll 1
    for (int c = 0; c < NCH; ++c) {
        // Issue chunk c+2 into slot (c+2)&3. Tail iterations re-issue the
        // last chunk into dead slots (never read again) — harmless, in-bounds.
        int cn = min(c + 2, NCH - 1);
        uint32_t dst = (uint32_t)__cvta_generic_to_shared(&sb[(c + 2) & 3][0][t]);
        const float4* src = ip + cn * 8;
        #pragma unroll
        for (int j = 0; j < 8; ++j)
            cp16(dst + j * (32 * 16), src + j);
        asm volatile("cp.async.commit_group;");

        // Wait until chunk c has landed (<= 2 groups still in flight).
        asm volatile("cp.async.wait_group 2;");
        // Single warp per block and each thread reads only what it wrote:
        // no barrier needed.

        int s4 = c & 3;
        #pragma unroll
        for (int q = 0; q < 4; ++q) {
            float4 A = sb[s4][2 * q][t];
            float4 C = sb[s4][2 * q + 1][t];
            float4 r;
            r.x = stepQ(A.x, A.y, SMS, GW, p);
            r.y = stepQ(A.z, A.w, SMS, GW, p);
            r.z = stepQ(C.x, C.y, SMS, GW, p);
            r.w = stepQ(C.z, C.w, SMS, GW, p);
            qo[c * 4 + q] = r;
        }
    }

    // Q[0]: roll wraps the FINAL state to t=0 — one extra step, t=0 inputs.
    float2 x0 = reinterpret_cast<const float2*>(in + (size_t)b * (2 * T_LEN))[0];
    out[(size_t)b * T_LEN] = stepQ(x0.x, x0.y, SMS, GW, p);
}

extern "C" void kernel_launch(void* const* d_in, const int* in_sizes, int n_in,
                              void* d_out, int out_size)
{
    const float* in = (const float*)d_in[0];
    int B = in_sizes[0] / (2 * T_LEN);
    int block = 32;                       // 1 warp/block -> ~all SMs, no sharing
    int grid  = (B + block - 1) / block;
    hirnn_kernel<<<grid, block>>>(in, (float*)d_out,
                                  (const float*)d_in[1], (const float*)d_in[2],
                                  (const float*)d_in[3], (const float*)d_in[4],
                                  (const float*)d_in[5], (const float*)d_in[6],
                                  (const float*)d_in[7], B);
}

// round 13
// speedup vs baseline: 2.0672x; 1.0745x over previous
#include <cuda_runtime.h>
#include <cstdint>

#define T_LEN 1024
#define NCH   64          // 64 chunks of 16 timesteps (8 float4 per row)

struct Pr {
    float INSC, SMSC, SUB10, CRAK10, RecK, kGW, inv10, cexp2, lgC, argC;
};

__device__ __forceinline__ float ex2f(float x) {
    float r; asm("ex2.approx.ftz.f32 %0, %1;" : "=f"(r) : "f"(x)); return r;
}

__device__ __forceinline__ void cp16(uint32_t smem_dst, const void* gsrc) {
    asm volatile("cp.async.ca.shared.global [%0], [%1], 16;"
                 :: "r"(smem_dst), "l"(gsrc));
}

// One scan step. State: arg = fma(SMSc, cexp2, lgC) (pre-evaluated exp input),
// tf = 10*SMSc/SMSC, ns = SMSc (clipped), GW. COEFF is folded into the
// exponent; the SMSC clip is deferred via monotonicity (cexp2 <= 0, inv10 > 0):
//   fma(min(s,SMSC), cexp2, lgC) == max(fma(s,cexp2,lgC), argC)
//   min(s,SMSC)*inv10            == min(s*inv10, 10)
// Returns Q[t] for the state ENTERING the step (reference's roll(1)).
__device__ __forceinline__ float stepQ(float Prec, float PET,
                                       float& arg, float& tf, float& ns,
                                       float& GW, const Pr& p)
{
    float cap  = ex2f(arg);                      // COEFF * exp(-SQ*frac)
    float INT  = fminf(fminf(p.INSC, PET), Prec);
    float INR  = Prec - INT;
    float POT  = PET - INT;
    float ETS  = fminf(POT, tf);
    float a1   = fmaf(-p.SUB10,  tf, 1.0f);      // 1 - SUB*frac
    float a2   = fmaf(-p.CRAK10, tf, 1.0f);      // 1 - CRAK*frac
    float g    = a1 * a2;
    float base = ns - ETS;
    float RMO  = fminf(INR, cap);                // heaviside blend == min
    float s    = fmaf(RMO, g, base);             // next SMS (pre-clip)
    float h    = RMO * a1;                       // RMO - SRUN
    float ns2  = fminf(s, p.SMSC);
    float RECn = h + (base - ns2);               // REC + overflow (s cancels)
    float Q    = fmaf(p.RecK, GW, INR - h);      // (IRUN+SRUN) + BAS
    GW  = fmaf(p.kGW, GW, RECn);                 // GW*(1-RecK) + RECn
    arg = fmaxf(fmaf(s, p.cexp2, p.lgC), p.argC);
    tf  = fminf(s * p.inv10, 10.0f);
    ns  = ns2;
    return Q;
}

__global__ void __launch_bounds__(32)
hirnn_kernel(const float* __restrict__ in, float* __restrict__ out,
             const float* __restrict__ pINSC, const float* __restrict__ pCOEFF,
             const float* __restrict__ pSQ,   const float* __restrict__ pSMSC,
             const float* __restrict__ pSUB,  const float* __restrict__ pCRAK,
             const float* __restrict__ pRecK, int B)
{
    // [slot][row][slice] with slice padded 8->9 float4: conflict-free for
    // both the cp.async store phases and the per-thread LDS.128 reads.
    __shared__ float4 sb[4][32][9];

    int t = threadIdx.x;
    int b = blockIdx.x * 32 + t;
    bool active = (b < B);
    int brow = min(b, B - 1);

    Pr p;
    p.INSC      = fminf(fmaxf(pINSC[0]  * 5.0f,   0.5f),   5.0f);
    float COEFF = fminf(fmaxf(pCOEFF[0] * 400.0f, 50.0f),  400.0f);
    float SQ    = fminf(fmaxf(pSQ[0]    * 6.0f,   0.0f),   6.0f);
    p.SMSC      = fminf(fmaxf(pSMSC[0]  * 500.0f, 50.0f),  500.0f);
    float SUB   = fminf(fmaxf(pSUB[0],            0.0f),   1.0f);
    float CRAK  = fminf(fmaxf(pCRAK[0],           0.0f),   1.0f);
    p.RecK      = fminf(fmaxf(pRecK[0]  * 0.3f,   0.003f), 0.3f);
    p.kGW       = 1.0f - p.RecK;
    float invS  = 1.0f / p.SMSC;
    p.inv10     = 10.0f * invS;
    p.SUB10     = SUB  * 0.1f;
    p.CRAK10    = CRAK * 0.1f;
    p.cexp2     = -SQ * invS * 1.44269504088896f; // exp(x)=exp2(x*log2e)
    p.lgC       = __log2f(COEFF);                 // fold COEFF into exponent
    p.argC      = fmaf(p.SMSC, p.cexp2, p.lgC);   // arg at s >= SMSC

    // Cooperative coalesced load geometry: lane l fetches 16B slice (l&7) of
    // row warp0 + 4k + (l>>3), rounds k=0..7 cover all 32 rows. Each cp.async
    // instruction touches 4 contiguous 128B lines (coalesced).
    const char* inb = (const char*)in;
    int warp0 = blockIdx.x * 32;
    int rsel  = t >> 3;
    int ssel  = t & 7;

    const char* gp[8];
    uint32_t    sp[8];
    #pragma unroll
    for (int k = 0; k < 8; ++k) {
        int row = min(warp0 + 4 * k + rsel, B - 1);
        gp[k] = inb + (size_t)row * (2 * T_LEN * 4) + ssel * 16;
        sp[k] = (uint32_t)__cvta_generic_to_shared(&sb[0][4 * k + rsel][ssel]);
    }
    const uint32_t SLOT = sizeof(float4) * 32 * 9;   // bytes per slot

    float4* qo = reinterpret_cast<float4*>(out + (size_t)brow * T_LEN);

    float arg = p.lgC, tf = 0.0f, ns = 0.0f, GW = 0.0f;

    // Prologue: chunks 0 and 1 (pipeline distance 2 => ~32 steps of cover).
    #pragma unroll
    for (int c0 = 0; c0 < 2; ++c0) {
        #pragma unroll
        for (int k = 0; k < 8; ++k)
            cp16(sp[k] + c0 * SLOT, gp[k] + c0 * 128);
        asm volatile("cp.async.commit_group;");
    }

    #pragma unroll 1
    for (int c = 0; c < NCH; ++c) {
        // Issue chunk c+2 into slot (c+2)&3; tail re-issues last chunk into
        // dead slots (never read again) — harmless, in-bounds.
        int cn = min(c + 2, NCH - 1);
        uint32_t so = ((c + 2) & 3) * SLOT;
        #pragma unroll
        for (int k = 0; k < 8; ++k)
            cp16(sp[k] + so, gp[k] + cn * 128);
        asm volatile("cp.async.commit_group;");

        // Chunk c complete when <= 2 groups remain in flight. Single warp,
        // LSU-ordered LDGSTS: no barrier needed.
        asm volatile("cp.async.wait_group 2;");

        int s4 = c & 3;
        #pragma unroll
        for (int q = 0; q < 4; ++q) {
            float4 A = sb[s4][t][2 * q];
            float4 C = sb[s4][t][2 * q + 1];
            float4 r;
            r.x = stepQ(A.x, A.y, arg, tf, ns, GW, p);
            r.y = stepQ(A.z, A.w, arg, tf, ns, GW, p);
            r.z = stepQ(C.x, C.y, arg, tf, ns, GW, p);
            r.w = stepQ(C.z, C.w, arg, tf, ns, GW, p);
            if (active) qo[c * 4 + q] = r;
        }
    }

    // Q[0]: roll wraps the FINAL state to t=0 — one extra step, t=0 inputs.
    float2 x0 = *reinterpret_cast<const float2*>(inb + (size_t)brow * (2 * T_LEN * 4));
    float q0 = stepQ(x0.x, x0.y, arg, tf, ns, GW, p);
    if (active) out[(size_t)b * T_LEN] = q0;
}

extern "C" void kernel_launch(void* const* d_in, const int* in_sizes, int n_in,
                              void* d_out, int out_size)
{
    const float* in = (const float*)d_in[0];
    int B = in_sizes[0] / (2 * T_LEN);
    int block = 32;                       // 1 warp/block -> ~all SMs, no sharing
    int grid  = (B + block - 1) / block;
    hirnn_kernel<<<grid, block>>>(in, (float*)d_out,
                                  (const float*)d_in[1], (const float*)d_in[2],
                                  (const float*)d_in[3], (const float*)d_in[4],
                                  (const float*)d_in[5], (const float*)d_in[6],
                                  (const float*)d_in[7], B);
}